// round 4
// baseline (speedup 1.0000x reference)
#include <cuda_runtime.h>
#include <cuda_bf16.h>

#define BATCH 16
#define NPTS  1024
#define CDIM  64

// -------- scratch (__device__ globals, allocation-free rule) --------
__device__ float         g_r[BATCH * NPTS * CDIM];      // x@W_root + b_rel (fp32)
__device__ __nv_bfloat16 g_yT_hi[BATCH * CDIM * NPTS];  // (x@W_rel)^T hi, [b][c][j]
__device__ __nv_bfloat16 g_yT_lo[BATCH * CDIM * NPTS];  // lo residual

// ===================== helpers =====================
__device__ __forceinline__ unsigned smem_u32(const void* p) {
    unsigned a;
    asm("{ .reg .u64 t; cvta.to.shared.u64 t, %1; cvt.u32.u64 %0, t; }"
        : "=r"(a) : "l"(p));
    return a;
}
#define CP_ASYNC16(dst, src) \
    asm volatile("cp.async.cg.shared.global [%0], [%1], 16;" :: "r"(dst), "l"(src))
#define CP_COMMIT() asm volatile("cp.async.commit_group;" ::: "memory")
#define CP_WAIT0()  asm volatile("cp.async.wait_group 0;" ::: "memory")
#define STS128(addr, r0, r1, r2, r3) \
    asm volatile("st.shared.v4.b32 [%0], {%1,%2,%3,%4};" \
                 :: "r"(addr), "r"(r0), "r"(r1), "r"(r2), "r"(r3) : "memory")
#define MBAR_INIT(addr, cnt) \
    asm volatile("mbarrier.init.shared.b64 [%0], %1;" :: "r"(addr), "r"(cnt) : "memory")
#define MBAR_ARRIVE(addr) \
    asm volatile("mbarrier.arrive.shared.b64 _, [%0];" :: "r"(addr) : "memory")

__device__ __forceinline__ void mbar_wait(unsigned mbar, unsigned parity) {
    unsigned done;
    asm volatile("{ .reg .pred p; mbarrier.try_wait.parity.acquire.cta.shared::cta.b64 p, [%1], %2; selp.b32 %0, 1, 0, p; }"
                 : "=r"(done) : "r"(mbar), "r"(parity) : "memory");
    if (!done) {
        asm volatile("{ .reg .pred P1; WL_%=: mbarrier.try_wait.parity.acquire.cta.shared::cta.b64 P1, [%0], %1, 0x989680; @P1 bra.uni WD_%=; bra.uni WL_%=; WD_%=: }"
                     :: "r"(mbar), "r"(parity) : "memory");
    }
}

__device__ __forceinline__ unsigned swz(unsigned off) { return off ^ ((off >> 3) & 0x70); }

__device__ __forceinline__ void ldx4(unsigned* r, unsigned addr) {
    asm volatile("ldmatrix.sync.aligned.m8n8.x4.shared.b16 {%0,%1,%2,%3}, [%4];"
                 : "=r"(r[0]), "=r"(r[1]), "=r"(r[2]), "=r"(r[3]) : "r"(addr));
}
__device__ __forceinline__ void mma16816(float* d, const unsigned* a,
                                         unsigned b0, unsigned b1) {
    asm volatile("mma.sync.aligned.m16n8k16.row.col.f32.bf16.bf16.f32 "
                 "{%0,%1,%2,%3}, {%4,%5,%6,%7}, {%8,%9}, {%0,%1,%2,%3};"
                 : "+f"(d[0]), "+f"(d[1]), "+f"(d[2]), "+f"(d[3])
                 : "r"(a[0]), "r"(a[1]), "r"(a[2]), "r"(a[3]), "r"(b0), "r"(b1));
}

// ===================== Stage 1 =====================
// y = x@W_rel (-> transposed bf16 hi/lo), r = x@W_root + b_rel (fp32)
__global__ __launch_bounds__(256) void stage1_kernel(
    const float* __restrict__ x, const float* __restrict__ W_rel,
    const float* __restrict__ b_rel, const float* __restrict__ W_root)
{
    __shared__ float xs[64][64];   // transposed x tile
    __shared__ float wr[64][64];
    __shared__ float wo[64][64];

    const int tid  = threadIdx.x;
    const int row0 = blockIdx.x * 64;

    for (int t = tid; t < 64 * 16; t += 256) {
        const int r = t >> 4, c4 = (t & 15) << 2;
        *(float4*)&wr[r][c4] = *(const float4*)&W_rel[r * 64 + c4];
        *(float4*)&wo[r][c4] = *(const float4*)&W_root[r * 64 + c4];
    }
    for (int t = tid; t < 64 * 16; t += 256) {
        const int r = t >> 4, c4 = (t & 15) << 2;
        float4 v = *(const float4*)&x[(row0 + r) * 64 + c4];
        xs[c4 + 0][r] = v.x; xs[c4 + 1][r] = v.y;
        xs[c4 + 2][r] = v.z; xs[c4 + 3][r] = v.w;
    }
    __syncthreads();

    const int ty = tid >> 4, tx = tid & 15;
    float accY[4][4] = {}, accR[4][4] = {};

#pragma unroll 8
    for (int k = 0; k < 64; k++) {
        const float4 a  = *(const float4*)&xs[k][ty * 4];
        const float4 by = *(const float4*)&wr[k][tx * 4];
        const float4 br = *(const float4*)&wo[k][tx * 4];
        const float av[4]  = {a.x, a.y, a.z, a.w};
        const float byv[4] = {by.x, by.y, by.z, by.w};
        const float brv[4] = {br.x, br.y, br.z, br.w};
#pragma unroll
        for (int r = 0; r < 4; r++)
#pragma unroll
            for (int c = 0; c < 4; c++) {
                accY[r][c] = fmaf(av[r], byv[c], accY[r][c]);
                accR[r][c] = fmaf(av[r], brv[c], accR[r][c]);
            }
    }

    float4 brel = *(const float4*)&b_rel[tx * 4];
    const float brelv[4] = {brel.x, brel.y, brel.z, brel.w};

    const int b  = row0 >> 10;
    const int jg = (row0 & 1023) + ty * 4;

#pragma unroll
    for (int r = 0; r < 4; r++) {
        const int grow = row0 + ty * 4 + r;
        float4 orr;
        orr.x = accR[r][0] + brelv[0]; orr.y = accR[r][1] + brelv[1];
        orr.z = accR[r][2] + brelv[2]; orr.w = accR[r][3] + brelv[3];
        *(float4*)&g_r[grow * 64 + tx * 4] = orr;
    }
#pragma unroll
    for (int c = 0; c < 4; c++) {
        unsigned hp[2], lp[2];
#pragma unroll
        for (int p = 0; p < 2; p++) {
            float v0 = accY[2 * p + 0][c], v1 = accY[2 * p + 1][c];
            __nv_bfloat16 h0 = __float2bfloat16(v0);
            __nv_bfloat16 h1 = __float2bfloat16(v1);
            __nv_bfloat16 l0 = __float2bfloat16(v0 - __bfloat162float(h0));
            __nv_bfloat16 l1 = __float2bfloat16(v1 - __bfloat162float(h1));
            hp[p] = (unsigned)__bfloat16_as_ushort(h0) | ((unsigned)__bfloat16_as_ushort(h1) << 16);
            lp[p] = (unsigned)__bfloat16_as_ushort(l0) | ((unsigned)__bfloat16_as_ushort(l1) << 16);
        }
        const long idx = ((long)(b * 64 + tx * 4 + c) << 10) + jg;
        *(uint2*)&g_yT_hi[idx] = make_uint2(hp[0], hp[1]);
        *(uint2*)&g_yT_lo[idx] = make_uint2(lp[0], lp[1]);
    }
}

// ===================== Stage 2 (warp-specialized) =====================
// out[b, i0:i0+64, :] = (adj*we[ea]) @ y + r
#define NCHUNK   16
#define NST      3
#define STAGE_SZ 32768
#define OFF_ALO  8192
#define OFF_BHI  16384
#define OFF_BAR  (NST * STAGE_SZ)          // 98304
#define SMEM_DYN (OFF_BAR + 64)
// full[s] @ OFF_BAR + s*8 ; empty[s] @ OFF_BAR + 24 + s*8

struct Chunk { float4 a[4]; int4 e[4]; };

__device__ __forceinline__ void ldg_chunk(const float* __restrict__ adj,
                                          const int* __restrict__ ea,
                                          long rowbase, int j0, int jb, Chunk& c) {
#pragma unroll
    for (int q = 0; q < 4; q++) {
        const long off = rowbase + j0 + jb + q * 4;
        c.a[q] = __ldg((const float4*)(adj + off));
        c.e[q] = __ldg((const int4*)(ea + off));
    }
}

__device__ __forceinline__ float wsel(int e, float w0, float w1, float w2, float w3) {
    return e == 0 ? w0 : (e == 1 ? w1 : (e == 2 ? w2 : w3));
}

// converts 16 values at (row, col jb..jb+15) -> bf16 hi @ abase, lo @ abase+8192
__device__ __forceinline__ void convert_sts(unsigned abase, int row, int jb,
                                            float w0, float w1, float w2, float w3,
                                            const Chunk& c) {
    unsigned hp[8], lp[8];
#pragma unroll
    for (int q = 0; q < 4; q++) {
        const float av[4] = {c.a[q].x, c.a[q].y, c.a[q].z, c.a[q].w};
        const int   ev[4] = {c.e[q].x, c.e[q].y, c.e[q].z, c.e[q].w};
#pragma unroll
        for (int p = 0; p < 2; p++) {
            float v0 = av[2 * p + 0] * wsel(ev[2 * p + 0], w0, w1, w2, w3);
            float v1 = av[2 * p + 1] * wsel(ev[2 * p + 1], w0, w1, w2, w3);
            __nv_bfloat16 h0 = __float2bfloat16(v0);
            __nv_bfloat16 h1 = __float2bfloat16(v1);
            __nv_bfloat16 l0 = __float2bfloat16(v0 - __bfloat162float(h0));
            __nv_bfloat16 l1 = __float2bfloat16(v1 - __bfloat162float(h1));
            hp[q * 2 + p] = (unsigned)__bfloat16_as_ushort(h0) |
                            ((unsigned)__bfloat16_as_ushort(h1) << 16);
            lp[q * 2 + p] = (unsigned)__bfloat16_as_ushort(l0) |
                            ((unsigned)__bfloat16_as_ushort(l1) << 16);
        }
    }
    const unsigned o = row * 128 + jb * 2;
    STS128(abase + swz(o),               hp[0], hp[1], hp[2], hp[3]);
    STS128(abase + swz(o + 16),          hp[4], hp[5], hp[6], hp[7]);
    STS128(abase + OFF_ALO + swz(o),      lp[0], lp[1], lp[2], lp[3]);
    STS128(abase + OFF_ALO + swz(o + 16), lp[4], lp[5], lp[6], lp[7]);
}

__device__ __forceinline__ void consumer_chunk(
    unsigned stage, unsigned aRowOff, unsigned aColX,
    unsigned bRowOff, unsigned bColX, float acc[8][4])
{
    const unsigned aHi = stage;
    const unsigned aLo = stage + OFF_ALO;
    const unsigned bHi = stage + OFF_BHI;
    const unsigned bLo = stage + OFF_BHI + 8192;
#pragma unroll
    for (int kh = 0; kh < 2; kh++) {
        unsigned ah[2][4], al[2][4];
        ldx4(ah[0], aHi + aRowOff + (((2 * kh + 0) * 32) ^ aColX));
        ldx4(ah[1], aHi + aRowOff + (((2 * kh + 1) * 32) ^ aColX));
        ldx4(al[0], aLo + aRowOff + (((2 * kh + 0) * 32) ^ aColX));
        ldx4(al[1], aLo + aRowOff + (((2 * kh + 1) * 32) ^ aColX));
#pragma unroll
        for (int nt = 0; nt < 8; nt++) {
            unsigned bb[4];
            ldx4(bb, bHi + bRowOff + nt * 1024 + ((kh * 64) ^ bColX));
            mma16816(acc[nt], ah[0], bb[0], bb[1]);
            mma16816(acc[nt], ah[1], bb[2], bb[3]);
            mma16816(acc[nt], al[0], bb[0], bb[1]);
            mma16816(acc[nt], al[1], bb[2], bb[3]);
        }
#pragma unroll
        for (int nt = 0; nt < 8; nt++) {
            unsigned bb[4];
            ldx4(bb, bLo + bRowOff + nt * 1024 + ((kh * 64) ^ bColX));
            mma16816(acc[nt], ah[0], bb[0], bb[1]);
            mma16816(acc[nt], ah[1], bb[2], bb[3]);
        }
    }
}

__global__ __launch_bounds__(256, 2) void stage2_kernel(
    const float* __restrict__ adj, const int* __restrict__ ea,
    const float* __restrict__ w_edge, float* __restrict__ out)
{
    extern __shared__ char smem_raw[];
    const unsigned sbase = smem_u32(smem_raw);

    const int tid  = threadIdx.x;
    const int lane = tid & 31, wid = tid >> 5;
    const int b  = blockIdx.x >> 4;
    const int i0 = (blockIdx.x & 15) * 64;

    if (tid == 0) {
#pragma unroll
        for (int s = 0; s < NST; s++) {
            MBAR_INIT(sbase + OFF_BAR + s * 8, 128);        // full
            MBAR_INIT(sbase + OFF_BAR + 24 + s * 8, 128);   // empty
        }
    }
    __syncthreads();

    if (wid < 4) {
        // ---------------- producers (128 threads) ----------------
        const float w0 = __ldg(w_edge + 0), w1 = __ldg(w_edge + 1),
                    w2 = __ldg(w_edge + 2), w3 = __ldg(w_edge + 3);
        const int  prow = tid >> 1;            // 0..63
        const int  jb   = (tid & 1) * 32;      // 0 / 32
        const long rowbase = ((long)b << 20) + (long)(i0 + prow) * NPTS;

        const int      brow = tid & 63, btile = tid >> 6;
        const __nv_bfloat16* bsrc0 =
            (btile ? g_yT_lo : g_yT_hi) + (((long)(b * 64 + brow)) << 10);
        const unsigned bdstb = OFF_BHI + btile * 8192;

        Chunk h0, h1;
        ldg_chunk(adj, ea, rowbase, 0, jb, h0);
        ldg_chunk(adj, ea, rowbase, 0, jb + 16, h1);

        int s = 0, ph = 1;
#pragma unroll 1
        for (int t = 0; t < NCHUNK; t++) {
            const unsigned stage = sbase + s * STAGE_SZ;
            mbar_wait(sbase + OFF_BAR + 24 + s * 8, (unsigned)ph);

            // B tiles via cp.async (8 x 16B per thread)
            {
                const __nv_bfloat16* bsrc = bsrc0 + t * 64;
#pragma unroll
                for (int v = 0; v < 8; v++)
                    CP_ASYNC16(stage + bdstb + swz(brow * 128 + v * 16), bsrc + v * 8);
                CP_COMMIT();
            }
            convert_sts(stage, prow, jb, w0, w1, w2, w3, h0);
            if (t + 1 < NCHUNK) ldg_chunk(adj, ea, rowbase, (t + 1) * 64, jb, h0);
            convert_sts(stage, prow, jb + 16, w0, w1, w2, w3, h1);
            if (t + 1 < NCHUNK) ldg_chunk(adj, ea, rowbase, (t + 1) * 64, jb + 16, h1);

            CP_WAIT0();
            MBAR_ARRIVE(sbase + OFF_BAR + s * 8);
            if (++s == NST) { s = 0; ph ^= 1; }
        }
    } else {
        // ---------------- consumers (128 threads) ----------------
        const int cw = wid - 4;                 // 0..3 -> rows cw*16
        const int l8 = lane & 7, mm = lane >> 3;
        const unsigned aRowOff = (unsigned)(cw * 16 + (mm & 1) * 8 + l8) * 128;
        const unsigned aColX   = ((unsigned)(mm >> 1) * 16) ^ ((unsigned)l8 << 4);
        const unsigned bRowOff = (unsigned)l8 * 128;
        const unsigned bColX   = ((unsigned)mm * 16) ^ ((unsigned)l8 << 4);

        float acc[8][4] = {};

        int s = 0, ph = 0;
#pragma unroll 1
        for (int t = 0; t < NCHUNK; t++) {
            mbar_wait(sbase + OFF_BAR + s * 8, (unsigned)ph);
            consumer_chunk(sbase + s * STAGE_SZ, aRowOff, aColX, bRowOff, bColX, acc);
            MBAR_ARRIVE(sbase + OFF_BAR + 24 + s * 8);
            if (++s == NST) { s = 0; ph ^= 1; }
        }

        // epilogue: add r, store
        const int gid = lane >> 2, tig = lane & 3;
        const int grow = b * NPTS + i0 + cw * 16 + gid;
#pragma unroll
        for (int nt = 0; nt < 8; nt++) {
            const int  col  = nt * 8 + tig * 2;
            const long idx0 = (long)grow * 64 + col;
            const long idx1 = (long)(grow + 8) * 64 + col;
            const float2 r0 = *(const float2*)&g_r[idx0];
            const float2 r1 = *(const float2*)&g_r[idx1];
            float2 o0, o1;
            o0.x = acc[nt][0] + r0.x; o0.y = acc[nt][1] + r0.y;
            o1.x = acc[nt][2] + r1.x; o1.y = acc[nt][3] + r1.y;
            *(float2*)&out[idx0] = o0;
            *(float2*)&out[idx1] = o1;
        }
    }
}

// ===================== launch =====================
extern "C" void kernel_launch(void* const* d_in, const int* in_sizes, int n_in,
                              void* d_out, int out_size)
{
    const float* x      = (const float*)d_in[0];
    const float* adj    = (const float*)d_in[1];
    const int*   ea     = (const int*)d_in[2];
    const float* W_rel  = (const float*)d_in[3];
    const float* b_rel  = (const float*)d_in[4];
    const float* W_root = (const float*)d_in[5];
    const float* w_edge = (const float*)d_in[6];
    float* out = (float*)d_out;

    static bool attr_set = false;
    if (!attr_set) {
        cudaFuncSetAttribute(stage2_kernel,
                             cudaFuncAttributeMaxDynamicSharedMemorySize, SMEM_DYN);
        attr_set = true;
    }

    stage1_kernel<<<(BATCH * NPTS) / 64, 256>>>(x, W_rel, b_rel, W_root);
    stage2_kernel<<<BATCH * (NPTS / 64), 256, SMEM_DYN>>>(adj, ea, w_edge, out);
}